// round 1
// baseline (speedup 1.0000x reference)
#include <cuda_runtime.h>
#include <cuda_bf16.h>
#include <math.h>
#include <stdint.h>

// ---------------------------------------------------------------------------
// Shapes (compile-time constants for this problem)
// ---------------------------------------------------------------------------
#define BATCH 8192
#define DIN   4096
#define DMODEL 512
#define FDIM  2048
#define NH    3
#define HD    256
#define OUTD  896

// GEMM tile config
#define TB 256
#define BM 128
#define BN 128
#define BKK 32
#define AST 36    // BK + 4  (conflict-free A smem stride)
#define BST 136   // BN + 8  (conflict-free B smem stride)

// Epilogue flags
#define F_B2   1   // add second bias (pos encoding)
#define F_GELU 2   // exact gelu
#define F_RES  4   // add residual read from res[r*ldc+c]
#define F_DUP  8   // duplicate write to out2

// ---------------------------------------------------------------------------
// Scratch (static device globals; allocation at module load is allowed)
// ---------------------------------------------------------------------------
__device__ float g_h  [BATCH * DMODEL];
__device__ float g_mem[BATCH * DMODEL];
__device__ float g_t  [BATCH * DMODEL];
__device__ float g_u  [BATCH * DMODEL];
__device__ float g_ff [BATCH * FDIM];
__device__ float g_z  [BATCH * NH * HD];

// ---------------------------------------------------------------------------
// Helpers
// ---------------------------------------------------------------------------
__device__ __forceinline__ void cp16(float* sm, const float* gm) {
    unsigned s = (unsigned)__cvta_generic_to_shared(sm);
    asm volatile("cp.async.ca.shared.global [%0], [%1], 16;\n" :: "r"(s), "l"(gm));
}
__device__ __forceinline__ unsigned f2tf32(float f) {
    unsigned u;
    asm("cvt.rna.tf32.f32 %0, %1;" : "=r"(u) : "f"(f));
    return u;
}
__device__ __forceinline__ float gelu_exact(float v) {
    return 0.5f * v * (1.0f + erff(v * 0.70710678118654752f));
}

// ---------------------------------------------------------------------------
// Tiled tf32 GEMM: C[r,c] = sum_k A[r,k]*B[k,c] (+bias[c]) (+bias2) (gelu) (+res)
// A row-major [M,K] lda, B row-major [K,N] ldb, C row-major ldc.
// grid: (N/BN, M/BM, batch). No bounds checks: all dims divide tiles exactly.
// ---------------------------------------------------------------------------
template<int FLAGS>
__global__ void __launch_bounds__(TB, 2) gemm_tf32(
    const float* __restrict__ A, int lda, long sA,
    const float* __restrict__ B, int ldb, long sB,
    float* __restrict__ C, int ldc, long sC,
    int K,
    const float* __restrict__ bias, int sBias,
    const float* __restrict__ bias2,
    const float* __restrict__ res,
    float* __restrict__ out2)
{
    extern __shared__ float smem[];
    float* As = smem;                 // 2 * BM * AST floats
    float* Bs = smem + 2 * BM * AST;  // 2 * BKK * BST floats

    const int z = blockIdx.z;
    A += (long)z * sA;
    B += (long)z * sB;
    C += (long)z * sC;
    bias += (long)z * sBias;
    const float* resb = (FLAGS & F_RES) ? (res + (long)z * sC) : nullptr;

    const int tid  = threadIdx.x;
    const int lane = tid & 31;
    const int warp = tid >> 5;
    const int wm = warp & 3;   // 4 warps along M (32 rows each)
    const int wn = warp >> 2;  // 2 warps along N (64 cols each)
    const long mBase = (long)blockIdx.y * BM;
    const int  nBase = blockIdx.x * BN;

    float acc[2][8][4];
#pragma unroll
    for (int i = 0; i < 2; i++)
#pragma unroll
        for (int j = 0; j < 8; j++)
#pragma unroll
            for (int k = 0; k < 4; k++) acc[i][j][k] = 0.f;

    const float* Ag0 = A + mBase * lda;
    const float* Bg0 = B + nBase;

    const int numK = K / BKK;

    // ---- prologue: load tile 0 ----
    {
        float* d = As;
        const float* g = Ag0;
#pragma unroll
        for (int i = 0; i < 4; i++) {
            int f = i * TB + tid; int r = f >> 3; int c = (f & 7) * 4;
            cp16(d + r * AST + c, g + (long)r * lda + c);
        }
        float* db = Bs;
        const float* gb = Bg0;
#pragma unroll
        for (int i = 0; i < 4; i++) {
            int f = i * TB + tid; int r = f >> 5; int c = (f & 31) * 4;
            cp16(db + r * BST + c, gb + (long)r * ldb + c);
        }
        asm volatile("cp.async.commit_group;\n" ::: "memory");
    }

    for (int kt = 0; kt < numK; kt++) {
        asm volatile("cp.async.wait_group 0;\n" ::: "memory");
        __syncthreads();

        if (kt + 1 < numK) {
            int buf = (kt + 1) & 1;
            float* d = As + buf * (BM * AST);
            const float* g = Ag0 + (kt + 1) * BKK;
#pragma unroll
            for (int i = 0; i < 4; i++) {
                int f = i * TB + tid; int r = f >> 3; int c = (f & 7) * 4;
                cp16(d + r * AST + c, g + (long)r * lda + c);
            }
            float* db = Bs + buf * (BKK * BST);
            const float* gb = Bg0 + (long)((kt + 1) * BKK) * ldb;
#pragma unroll
            for (int i = 0; i < 4; i++) {
                int f = i * TB + tid; int r = f >> 5; int c = (f & 31) * 4;
                cp16(db + r * BST + c, gb + (long)r * ldb + c);
            }
            asm volatile("cp.async.commit_group;\n" ::: "memory");
        }

        const float* a_s = As + (kt & 1) * (BM * AST) + (wm * 32) * AST;
        const float* b_s = Bs + (kt & 1) * (BKK * BST) + wn * 64;

#pragma unroll
        for (int ks = 0; ks < BKK / 8; ks++) {
            unsigned af[2][4];
#pragma unroll
            for (int mi = 0; mi < 2; mi++) {
                const float* ap = a_s + (mi * 16 + (lane >> 2)) * AST + ks * 8 + (lane & 3);
                af[mi][0] = f2tf32(ap[0]);
                af[mi][1] = f2tf32(ap[8 * AST]);
                af[mi][2] = f2tf32(ap[4]);
                af[mi][3] = f2tf32(ap[8 * AST + 4]);
            }
            unsigned bf[8][2];
#pragma unroll
            for (int ni = 0; ni < 8; ni++) {
                const float* bp = b_s + (ks * 8 + (lane & 3)) * BST + ni * 8 + (lane >> 2);
                bf[ni][0] = f2tf32(bp[0]);
                bf[ni][1] = f2tf32(bp[4 * BST]);
            }
#pragma unroll
            for (int mi = 0; mi < 2; mi++)
#pragma unroll
                for (int ni = 0; ni < 8; ni++)
                    asm volatile(
                        "mma.sync.aligned.m16n8k8.row.col.f32.tf32.tf32.f32 "
                        "{%0,%1,%2,%3},{%4,%5,%6,%7},{%8,%9},{%0,%1,%2,%3};\n"
                        : "+f"(acc[mi][ni][0]), "+f"(acc[mi][ni][1]),
                          "+f"(acc[mi][ni][2]), "+f"(acc[mi][ni][3])
                        : "r"(af[mi][0]), "r"(af[mi][1]), "r"(af[mi][2]), "r"(af[mi][3]),
                          "r"(bf[ni][0]), "r"(bf[ni][1]));
        }
    }

    // ---- epilogue ----
    const int rBase = (int)mBase + wm * 32;
    const int cBase = nBase + wn * 64;
#pragma unroll
    for (int mi = 0; mi < 2; mi++) {
#pragma unroll
        for (int ni = 0; ni < 8; ni++) {
            int c = cBase + ni * 8 + (lane & 3) * 2;
            float b0 = bias[c], b1 = bias[c + 1];
            if (FLAGS & F_B2) { b0 += bias2[c]; b1 += bias2[c + 1]; }
#pragma unroll
            for (int half = 0; half < 2; half++) {
                int r = rBase + mi * 16 + (lane >> 2) + half * 8;
                float v0 = acc[mi][ni][half * 2 + 0] + b0;
                float v1 = acc[mi][ni][half * 2 + 1] + b1;
                if (FLAGS & F_GELU) { v0 = gelu_exact(v0); v1 = gelu_exact(v1); }
                long idx = (long)r * ldc + c;
                if (FLAGS & F_RES) {
                    float2 rr = *(const float2*)(resb + idx);
                    v0 += rr.x; v1 += rr.y;
                }
                float2 o = make_float2(v0, v1);
                *(float2*)(C + idx) = o;
                if (FLAGS & F_DUP) *(float2*)(out2 + idx) = o;
            }
        }
    }
}

// ---------------------------------------------------------------------------
// Row LayerNorm: out[row,:] = (x - mean)*rsqrt(var+eps)*g + b
// headMod > 0: gamma/beta indexed by (row % headMod)*C (per-head LN params).
// grid = rows, block = 128. Safe in-place.
// ---------------------------------------------------------------------------
__global__ void ln_kernel(const float* __restrict__ in, float* __restrict__ out,
                          const float* __restrict__ g, const float* __restrict__ b,
                          int C, int headMod)
{
    __shared__ float red[8];
    const int row = blockIdx.x;
    const float* x = in + (long)row * C;
    float* y = out + (long)row * C;
    const int go = headMod ? (row % headMod) * C : 0;

    float s = 0.f, s2 = 0.f;
    for (int i = threadIdx.x; i < C; i += 128) {
        float v = x[i]; s += v; s2 += v * v;
    }
#pragma unroll
    for (int o = 16; o; o >>= 1) {
        s  += __shfl_xor_sync(0xffffffffu, s, o);
        s2 += __shfl_xor_sync(0xffffffffu, s2, o);
    }
    const int w = threadIdx.x >> 5;
    if ((threadIdx.x & 31) == 0) { red[w] = s; red[4 + w] = s2; }
    __syncthreads();
    if (threadIdx.x == 0) {
        float ts = 0.f, ts2 = 0.f;
#pragma unroll
        for (int i = 0; i < 4; i++) { ts += red[i]; ts2 += red[4 + i]; }
        red[0] = ts; red[4] = ts2;
    }
    __syncthreads();
    const float mean = red[0] / C;
    const float var  = red[4] / C - mean * mean;
    const float inv  = rsqrtf(var + 1e-5f);
    for (int i = threadIdx.x; i < C; i += 128)
        y[i] = (x[i] - mean) * inv * g[go + i] + b[go + i];
}

// ---------------------------------------------------------------------------
// Launch
// ---------------------------------------------------------------------------
extern "C" void kernel_launch(void* const* d_in, const int* in_sizes, int n_in,
                              void* d_out, int out_size)
{
    const float* x      = (const float*)d_in[0];
    const float* w_in   = (const float*)d_in[1];
    const float* b_in   = (const float*)d_in[2];
    const float* pos    = (const float*)d_in[3];
    const float* ln1_g  = (const float*)d_in[4];
    const float* ln1_b  = (const float*)d_in[5];
    const float* wv_sa  = (const float*)d_in[6];
    const float* bv_sa  = (const float*)d_in[7];
    const float* wo_sa  = (const float*)d_in[8];
    const float* bo_sa  = (const float*)d_in[9];
    // d_in[10], d_in[11]: ln2_g / ln2_b — unused by the reference math
    const float* wv_ca  = (const float*)d_in[12];
    const float* bv_ca  = (const float*)d_in[13];
    const float* wo_ca  = (const float*)d_in[14];
    const float* bo_ca  = (const float*)d_in[15];
    const float* ln3_g  = (const float*)d_in[16];
    const float* ln3_b  = (const float*)d_in[17];
    const float* w_ff1  = (const float*)d_in[18];
    const float* b_ff1  = (const float*)d_in[19];
    const float* w_ff2  = (const float*)d_in[20];
    const float* b_ff2  = (const float*)d_in[21];
    const float* lnout_g= (const float*)d_in[22];
    const float* lnout_b= (const float*)d_in[23];
    const float* wh1    = (const float*)d_in[24];
    const float* bh1    = (const float*)d_in[25];
    const float* lnh_g  = (const float*)d_in[26];
    const float* lnh_b  = (const float*)d_in[27];
    const float* wh2    = (const float*)d_in[28];
    const float* bh2    = (const float*)d_in[29];
    float* out = (float*)d_out;

    float *h, *mem, *t, *u, *ff, *zz;
    cudaGetSymbolAddress((void**)&h,   g_h);
    cudaGetSymbolAddress((void**)&mem, g_mem);
    cudaGetSymbolAddress((void**)&t,   g_t);
    cudaGetSymbolAddress((void**)&u,   g_u);
    cudaGetSymbolAddress((void**)&ff,  g_ff);
    cudaGetSymbolAddress((void**)&zz,  g_z);

    const int SMB = (2 * BM * AST + 2 * BKK * BST) * (int)sizeof(float);  // 71680 B
    cudaFuncSetAttribute(gemm_tf32<F_B2 | F_DUP>, cudaFuncAttributeMaxDynamicSharedMemorySize, SMB);
    cudaFuncSetAttribute(gemm_tf32<0>,            cudaFuncAttributeMaxDynamicSharedMemorySize, SMB);
    cudaFuncSetAttribute(gemm_tf32<F_RES>,        cudaFuncAttributeMaxDynamicSharedMemorySize, SMB);
    cudaFuncSetAttribute(gemm_tf32<F_GELU>,       cudaFuncAttributeMaxDynamicSharedMemorySize, SMB);

    dim3 blk(TB);
    const int MG = BATCH / BM;  // 64

    // 1) h = x @ w_in + b_in + pos ; mem = h
    gemm_tf32<F_B2 | F_DUP><<<dim3(DMODEL / BN, MG, 1), blk, SMB>>>(
        x, DIN, 0, w_in, DMODEL, 0, h, DMODEL, 0, DIN, b_in, 0, pos, nullptr, mem);

    // 2) t = ln1(h)
    ln_kernel<<<BATCH, 128>>>(h, t, ln1_g, ln1_b, DMODEL, 0);

    // 3) u = t @ wv_sa + bv_sa
    gemm_tf32<0><<<dim3(DMODEL / BN, MG, 1), blk, SMB>>>(
        t, DMODEL, 0, wv_sa, DMODEL, 0, u, DMODEL, 0, DMODEL, bv_sa, 0, nullptr, nullptr, nullptr);

    // 4) h = h + u @ wo_sa + bo_sa
    gemm_tf32<F_RES><<<dim3(DMODEL / BN, MG, 1), blk, SMB>>>(
        u, DMODEL, 0, wo_sa, DMODEL, 0, h, DMODEL, 0, DMODEL, bo_sa, 0, nullptr, h, nullptr);

    // 5) u = mem @ wv_ca + bv_ca
    gemm_tf32<0><<<dim3(DMODEL / BN, MG, 1), blk, SMB>>>(
        mem, DMODEL, 0, wv_ca, DMODEL, 0, u, DMODEL, 0, DMODEL, bv_ca, 0, nullptr, nullptr, nullptr);

    // 6) h = h + u @ wo_ca + bo_ca
    gemm_tf32<F_RES><<<dim3(DMODEL / BN, MG, 1), blk, SMB>>>(
        u, DMODEL, 0, wo_ca, DMODEL, 0, h, DMODEL, 0, DMODEL, bo_ca, 0, nullptr, h, nullptr);

    // 7) t = ln3(h)
    ln_kernel<<<BATCH, 128>>>(h, t, ln3_g, ln3_b, DMODEL, 0);

    // 8) ff = gelu(t @ w_ff1 + b_ff1)
    gemm_tf32<F_GELU><<<dim3(FDIM / BN, MG, 1), blk, SMB>>>(
        t, DMODEL, 0, w_ff1, FDIM, 0, ff, FDIM, 0, DMODEL, b_ff1, 0, nullptr, nullptr, nullptr);

    // 9) h = h + ff @ w_ff2 + b_ff2
    gemm_tf32<F_RES><<<dim3(DMODEL / BN, MG, 1), blk, SMB>>>(
        ff, FDIM, 0, w_ff2, DMODEL, 0, h, DMODEL, 0, FDIM, b_ff2, 0, nullptr, h, nullptr);

    // 10) t = lnout(h)
    ln_kernel<<<BATCH, 128>>>(h, t, lnout_g, lnout_b, DMODEL, 0);

    // 11) z[:,hh,:] = gelu(t @ wh1[hh] + bh1[hh])   (batched over heads)
    gemm_tf32<F_GELU><<<dim3(HD / BN, MG, NH), blk, SMB>>>(
        t, DMODEL, 0, wh1, HD, (long)DMODEL * HD, zz, NH * HD, HD,
        DMODEL, bh1, HD, nullptr, nullptr, nullptr);

    // 12) z = ln_head(z)  (per-head gamma/beta, in place)
    ln_kernel<<<BATCH * NH, 128>>>(zz, zz, lnh_g, lnh_b, HD, NH);

    // 13) out[:,hh,:] = z[:,hh,:] @ wh2[hh] + bh2[hh]
    gemm_tf32<0><<<dim3(OUTD / BN, MG, NH), blk, SMB>>>(
        zz, NH * HD, HD, wh2, OUTD, (long)HD * OUTD, out, NH * OUTD, OUTD,
        HD, bh2, OUTD, nullptr, nullptr, nullptr);
}